// round 1
// baseline (speedup 1.0000x reference)
#include <cuda_runtime.h>
#include <math.h>

// Problem constants (fixed by the dataset)
#define T_TOK   8192          // B*S = 4*2048
#define H_DIM   1024
#define F_DIM   4096
#define E_NUM   8
#define A_NUM   (2 * T_TOK)   // total assignments (top_k = 2)

// ---------------- scratch (static device globals; no allocation allowed) -----
__device__ int   d_counts[E_NUM];
__device__ int   d_cursor[E_NUM];
__device__ int   d_off[E_NUM];
__device__ int   d_eidx[A_NUM];    // [t*2+j] -> expert id
__device__ float d_wt[A_NUM];      // [t*2+j] -> combine weight (normalized)
__device__ int   d_tok[A_NUM];     // [slot]  -> token id
__device__ int   d_slot[A_NUM];    // [t*2+j] -> slot
__device__ float d_hbuf[(size_t)A_NUM * F_DIM];  // 256 MB: gelu(x@w1+b1) rows
__device__ float d_ybuf[(size_t)A_NUM * H_DIM];  // 64 MB:  h@w2+b2 rows

// ---------------- small kernels ---------------------------------------------
__global__ void init_kernel() {
    int i = threadIdx.x;
    if (i < E_NUM) { d_counts[i] = 0; d_cursor[i] = 0; }
}

__global__ void router_kernel(const float* __restrict__ x,
                              const float* __restrict__ rw,
                              const float* __restrict__ rb) {
    int warp = (blockIdx.x * blockDim.x + threadIdx.x) >> 5;
    int lane = threadIdx.x & 31;
    if (warp >= T_TOK) return;
    const float* xr = x + (size_t)warp * H_DIM;
    float acc[E_NUM];
#pragma unroll
    for (int e = 0; e < E_NUM; e++) acc[e] = 0.f;
    for (int k = lane; k < H_DIM; k += 32) {
        float xv = xr[k];
        const float* r = rw + (size_t)k * E_NUM;
#pragma unroll
        for (int e = 0; e < E_NUM; e++) acc[e] += xv * r[e];
    }
#pragma unroll
    for (int off = 16; off; off >>= 1)
#pragma unroll
        for (int e = 0; e < E_NUM; e++)
            acc[e] += __shfl_down_sync(0xffffffffu, acc[e], off);
    if (lane == 0) {
        float l[E_NUM];
#pragma unroll
        for (int e = 0; e < E_NUM; e++) l[e] = acc[e] + rb[e];
        int i0 = 0;
#pragma unroll
        for (int e = 1; e < E_NUM; e++) if (l[e] > l[i0]) i0 = e;
        int i1 = -1;
#pragma unroll
        for (int e = 0; e < E_NUM; e++)
            if (e != i0 && (i1 < 0 || l[e] > l[i1])) i1 = e;
        // normalized top-2 softmax weights (Z cancels): exp(li-m)/(exp(l0-m)+exp(l1-m))
        float m  = l[i0];
        float p1 = __expf(l[i1] - m);
        float s  = 1.f + p1;
        d_eidx[2 * warp + 0] = i0;  d_wt[2 * warp + 0] = 1.f / s;
        d_eidx[2 * warp + 1] = i1;  d_wt[2 * warp + 1] = p1 / s;
        atomicAdd(&d_counts[i0], 1);
        atomicAdd(&d_counts[i1], 1);
    }
}

__global__ void offsets_kernel() {
    if (threadIdx.x == 0) {
        int acc = 0;
        for (int e = 0; e < E_NUM; e++) { d_off[e] = acc; acc += d_counts[e]; }
    }
}

__global__ void scatter_kernel() {
    int t = blockIdx.x * blockDim.x + threadIdx.x;
    if (t >= T_TOK) return;
#pragma unroll
    for (int j = 0; j < 2; j++) {
        int e   = d_eidx[2 * t + j];
        int pos = d_off[e] + atomicAdd(&d_cursor[e], 1);
        d_tok[pos] = t;
        d_slot[2 * t + j] = pos;
    }
}

// ---------------- GEMMs: 128x128 tile, BK=8, 256 threads, 8x8 per thread ----
__device__ __forceinline__ float gelu_tanh(float v) {
    float c = 0.7978845608028654f * (v + 0.044715f * v * v * v);
    return 0.5f * v * (1.f + tanhf(c));
}

// GEMM1: for expert e, rows = gathered x tokens, B = w1[e] (H x F), out = gelu(.+b1)
__global__ __launch_bounds__(256) void gemm1_kernel(const float* __restrict__ x,
                                                    const float* __restrict__ w1,
                                                    const float* __restrict__ b1) {
    int e   = blockIdx.z;
    int cnt = d_counts[e];
    int m0  = blockIdx.y * 128;
    if (m0 >= cnt) return;
    int off = d_off[e];
    int n0  = blockIdx.x * 128;
    const float* B = w1 + (size_t)e * H_DIM * F_DIM;

    __shared__ float As[8][128];
    __shared__ float Bs[8][128];

    int tid = threadIdx.x;
    int ar  = tid >> 1;            // A row in tile   0..127
    int ak  = (tid & 1) * 4;       // A k offset      0 or 4
    int arow_ok = (m0 + ar < cnt);
    const float* arow = x + (size_t)(arow_ok ? d_tok[off + m0 + ar] : d_tok[off]) * H_DIM;
    int bk  = tid >> 5;            // B k row 0..7
    int bn  = (tid & 31) * 4;      // B col offset
    int ty  = tid >> 4, tx = tid & 15;

    float acc[8][8];
#pragma unroll
    for (int i = 0; i < 8; i++)
#pragma unroll
        for (int j = 0; j < 8; j++) acc[i][j] = 0.f;

    for (int k0 = 0; k0 < H_DIM; k0 += 8) {
        float4 av = *(const float4*)(arow + k0 + ak);
        As[ak + 0][ar] = av.x; As[ak + 1][ar] = av.y;
        As[ak + 2][ar] = av.z; As[ak + 3][ar] = av.w;
        *(float4*)&Bs[bk][bn] = *(const float4*)(B + (size_t)(k0 + bk) * F_DIM + n0 + bn);
        __syncthreads();
#pragma unroll
        for (int k = 0; k < 8; k++) {
            float a[8], b[8];
            *(float4*)&a[0] = *(float4*)&As[k][ty * 8];
            *(float4*)&a[4] = *(float4*)&As[k][ty * 8 + 4];
            *(float4*)&b[0] = *(float4*)&Bs[k][tx * 8];
            *(float4*)&b[4] = *(float4*)&Bs[k][tx * 8 + 4];
#pragma unroll
            for (int i = 0; i < 8; i++)
#pragma unroll
                for (int j = 0; j < 8; j++) acc[i][j] += a[i] * b[j];
        }
        __syncthreads();
    }
#pragma unroll
    for (int i = 0; i < 8; i++) {
        int m = m0 + ty * 8 + i;
        if (m >= cnt) continue;
        float* hrow = d_hbuf + (size_t)(off + m) * F_DIM + n0 + tx * 8;
        const float* bb = b1 + (size_t)e * F_DIM + n0 + tx * 8;
#pragma unroll
        for (int j = 0; j < 8; j++) hrow[j] = gelu_tanh(acc[i][j] + bb[j]);
    }
}

// GEMM2: rows = contiguous h rows of this expert, B = w2[e] (F x H), out = .+b2
__global__ __launch_bounds__(256) void gemm2_kernel(const float* __restrict__ w2,
                                                    const float* __restrict__ b2) {
    int e   = blockIdx.z;
    int cnt = d_counts[e];
    int m0  = blockIdx.y * 128;
    if (m0 >= cnt) return;
    int off = d_off[e];
    int n0  = blockIdx.x * 128;
    const float* B = w2 + (size_t)e * F_DIM * H_DIM;

    __shared__ float As[8][128];
    __shared__ float Bs[8][128];

    int tid = threadIdx.x;
    int ar  = tid >> 1;
    int ak  = (tid & 1) * 4;
    int arow_ok = (m0 + ar < cnt);
    const float* arow = d_hbuf + (size_t)(off + (arow_ok ? (m0 + ar) : 0)) * F_DIM;
    int bk  = tid >> 5;
    int bn  = (tid & 31) * 4;
    int ty  = tid >> 4, tx = tid & 15;

    float acc[8][8];
#pragma unroll
    for (int i = 0; i < 8; i++)
#pragma unroll
        for (int j = 0; j < 8; j++) acc[i][j] = 0.f;

    for (int k0 = 0; k0 < F_DIM; k0 += 8) {
        float4 av = *(const float4*)(arow + k0 + ak);
        As[ak + 0][ar] = av.x; As[ak + 1][ar] = av.y;
        As[ak + 2][ar] = av.z; As[ak + 3][ar] = av.w;
        *(float4*)&Bs[bk][bn] = *(const float4*)(B + (size_t)(k0 + bk) * H_DIM + n0 + bn);
        __syncthreads();
#pragma unroll
        for (int k = 0; k < 8; k++) {
            float a[8], b[8];
            *(float4*)&a[0] = *(float4*)&As[k][ty * 8];
            *(float4*)&a[4] = *(float4*)&As[k][ty * 8 + 4];
            *(float4*)&b[0] = *(float4*)&Bs[k][tx * 8];
            *(float4*)&b[4] = *(float4*)&Bs[k][tx * 8 + 4];
#pragma unroll
            for (int i = 0; i < 8; i++)
#pragma unroll
                for (int j = 0; j < 8; j++) acc[i][j] += a[i] * b[j];
        }
        __syncthreads();
    }
#pragma unroll
    for (int i = 0; i < 8; i++) {
        int m = m0 + ty * 8 + i;
        if (m >= cnt) continue;
        float* yrow = d_ybuf + (size_t)(off + m) * H_DIM + n0 + tx * 8;
        const float* bb = b2 + (size_t)e * H_DIM + n0 + tx * 8;
#pragma unroll
        for (int j = 0; j < 8; j++) yrow[j] = acc[i][j] + bb[j];
    }
}

__global__ void combine_kernel(float* __restrict__ out) {
    int idx = blockIdx.x * blockDim.x + threadIdx.x;   // over T*H/4 float4s
    if (idx >= T_TOK * (H_DIM / 4)) return;
    int t  = idx >> 8;               // H/4 = 256
    int n4 = idx & 255;
    int   s0 = d_slot[2 * t + 0], s1 = d_slot[2 * t + 1];
    float w0 = d_wt[2 * t + 0],  w1 = d_wt[2 * t + 1];
    float4 a = *(const float4*)(d_ybuf + (size_t)s0 * H_DIM + n4 * 4);
    float4 b = *(const float4*)(d_ybuf + (size_t)s1 * H_DIM + n4 * 4);
    float4 o;
    o.x = w0 * a.x + w1 * b.x;
    o.y = w0 * a.y + w1 * b.y;
    o.z = w0 * a.z + w1 * b.z;
    o.w = w0 * a.w + w1 * b.w;
    *(float4*)(out + (size_t)t * H_DIM + n4 * 4) = o;
}

// ---------------- launch -----------------------------------------------------
extern "C" void kernel_launch(void* const* d_in, const int* in_sizes, int n_in,
                              void* d_out, int out_size) {
    const float* x  = (const float*)d_in[0];   // [4,2048,1024]
    const float* rw = (const float*)d_in[1];   // [1024,8]
    const float* rb = (const float*)d_in[2];   // [8]
    const float* w1 = (const float*)d_in[3];   // [8,1024,4096]
    const float* b1 = (const float*)d_in[4];   // [8,4096]
    const float* w2 = (const float*)d_in[5];   // [8,4096,1024]
    const float* b2 = (const float*)d_in[6];   // [8,1024]
    float* out = (float*)d_out;

    init_kernel<<<1, 32>>>();
    router_kernel<<<T_TOK / 4, 128>>>(x, rw, rb);
    offsets_kernel<<<1, 32>>>();
    scatter_kernel<<<(T_TOK + 255) / 256, 256>>>();

    dim3 g1(F_DIM / 128, T_TOK / 128, E_NUM);   // (32, 64, 8); tiles past count early-exit
    gemm1_kernel<<<g1, 256>>>(x, w1, b1);
    dim3 g2(H_DIM / 128, T_TOK / 128, E_NUM);   // (8, 64, 8)
    gemm2_kernel<<<g2, 256>>>(w2, b2);

    combine_kernel<<<(T_TOK * (H_DIM / 4) + 255) / 256, 256>>>(out);
}

// round 7
// speedup vs baseline: 1.3887x; 1.3887x over previous
#include <cuda_runtime.h>
#include <cstdint>
#include <math.h>

#define T_TOK   8192
#define H_DIM   1024
#define F_DIM   4096
#define E_NUM   8
#define A_NUM   (2 * T_TOK)

// ---------------- scratch: EXACTLY the R1 set (known-good) -------------------
__device__ int   d_counts[E_NUM];
__device__ int   d_cursor[E_NUM];
__device__ int   d_off[E_NUM];
__device__ int   d_eidx[A_NUM];
__device__ float d_wt[A_NUM];
__device__ int   d_tok[A_NUM];
__device__ int   d_slot[A_NUM];
__device__ float d_hbuf[(size_t)A_NUM * F_DIM];  // gelu(x@w1+b1) rows (fp32)
__device__ float d_ybuf[(size_t)A_NUM * H_DIM];  // h@w2+b2 rows (fp32)

// ---------------- new PTX (the ONLY new constructs vs R1) --------------------
__device__ __forceinline__ void mma_tf32(float* c, const uint32_t* a, uint32_t b0, uint32_t b1) {
    asm volatile("mma.sync.aligned.m16n8k8.row.col.f32.tf32.tf32.f32 "
                 "{%0,%1,%2,%3}, {%4,%5,%6,%7}, {%8,%9}, {%0,%1,%2,%3};"
                 : "+f"(c[0]), "+f"(c[1]), "+f"(c[2]), "+f"(c[3])
                 : "r"(a[0]), "r"(a[1]), "r"(a[2]), "r"(a[3]), "r"(b0), "r"(b1));
}
__device__ __forceinline__ void split_tf32(float x, uint32_t& hi, uint32_t& lo) {
    uint32_t h;
    asm("cvt.rna.tf32.f32 %0, %1;" : "=r"(h) : "f"(x));
    float r = x - __uint_as_float(h);
    asm("cvt.rna.tf32.f32 %0, %1;" : "=r"(lo) : "f"(r));
    hi = h;
}

// ---------------- small kernels (R1 verbatim) --------------------------------
__global__ void init_kernel() {
    int i = threadIdx.x;
    if (i < E_NUM) { d_counts[i] = 0; d_cursor[i] = 0; }
}

__global__ void router_kernel(const float* __restrict__ x,
                              const float* __restrict__ rw,
                              const float* __restrict__ rb) {
    int warp = (blockIdx.x * blockDim.x + threadIdx.x) >> 5;
    int lane = threadIdx.x & 31;
    if (warp >= T_TOK) return;
    const float* xr = x + (size_t)warp * H_DIM;
    float acc[E_NUM];
#pragma unroll
    for (int e = 0; e < E_NUM; e++) acc[e] = 0.f;
    for (int k = lane; k < H_DIM; k += 32) {
        float xv = xr[k];
        const float* r = rw + (size_t)k * E_NUM;
#pragma unroll
        for (int e = 0; e < E_NUM; e++) acc[e] += xv * r[e];
    }
#pragma unroll
    for (int off = 16; off; off >>= 1)
#pragma unroll
        for (int e = 0; e < E_NUM; e++)
            acc[e] += __shfl_down_sync(0xffffffffu, acc[e], off);
    if (lane == 0) {
        float l[E_NUM];
#pragma unroll
        for (int e = 0; e < E_NUM; e++) l[e] = acc[e] + rb[e];
        int i0 = 0;
#pragma unroll
        for (int e = 1; e < E_NUM; e++) if (l[e] > l[i0]) i0 = e;
        int i1 = -1;
#pragma unroll
        for (int e = 0; e < E_NUM; e++)
            if (e != i0 && (i1 < 0 || l[e] > l[i1])) i1 = e;
        float m  = l[i0];
        float p1 = __expf(l[i1] - m);
        float s  = 1.f + p1;
        d_eidx[2 * warp + 0] = i0;  d_wt[2 * warp + 0] = 1.f / s;
        d_eidx[2 * warp + 1] = i1;  d_wt[2 * warp + 1] = p1 / s;
        atomicAdd(&d_counts[i0], 1);
        atomicAdd(&d_counts[i1], 1);
    }
}

__global__ void offsets_kernel() {
    if (threadIdx.x == 0) {
        int acc = 0;
        for (int e = 0; e < E_NUM; e++) { d_off[e] = acc; acc += d_counts[e]; }
    }
}

__global__ void scatter_kernel() {
    int t = blockIdx.x * blockDim.x + threadIdx.x;
    if (t >= T_TOK) return;
#pragma unroll
    for (int j = 0; j < 2; j++) {
        int e   = d_eidx[2 * t + j];
        int pos = d_off[e] + atomicAdd(&d_cursor[e], 1);
        d_tok[pos] = t;
        d_slot[2 * t + j] = pos;
    }
}

// ---------------- grouped GEMM: R1 structure + tf32 mma core -----------------
__device__ __forceinline__ float gelu_tanh(float v) {
    float c = 0.7978845608028654f * (v + 0.044715f * v * v * v);
    return 0.5f * v * (1.f + tanhf(c));
}

#define BK      16
#define LDS_PAD 136   // row stride in floats -> fragment LDS bank-conflict-free

template <bool G1>
__global__ __launch_bounds__(256) void moe_gemm(const float* __restrict__ A_in,
                                                const float* __restrict__ W,
                                                const float* __restrict__ bias) {
    constexpr int K_TOT = G1 ? H_DIM : F_DIM;
    constexpr int N_TOT = G1 ? F_DIM : H_DIM;
    constexpr int NCH   = K_TOT / BK;

    int e   = blockIdx.z;
    int cnt = d_counts[e];
    int m0  = blockIdx.y * 128;
    if (m0 >= cnt) return;
    int off = d_off[e];
    int n0  = blockIdx.x * 128;
    const float* B = W + (size_t)e * (size_t)K_TOT * N_TOT;

    __shared__ float As[BK][LDS_PAD];
    __shared__ float Bs[BK][LDS_PAD];

    int tid  = threadIdx.x;
    int lane = tid & 31;
    int w    = tid >> 5;
    int wm   = (w >> 2) * 64;   // warp tile 64x32, warps 2x4
    int wn   = (w & 3) * 32;
    int gid  = lane >> 2;       // fragment group id (row)
    int tg   = lane & 3;        // thread-in-group (col)

    // A staging roles (R1 verbatim): row = tid>>1, k-offset (tid&1)*4
    int ar = tid >> 1;
    int ak = (tid & 1) * 4;
    int arow_ok = (m0 + ar < cnt);
    const float* Abase = G1 ? A_in : d_hbuf;
    const float* arow;
    if (G1) arow = Abase + (size_t)d_tok[off + (arow_ok ? m0 + ar : 0)] * K_TOT;
    else    arow = Abase + (size_t)(off + (arow_ok ? m0 + ar : 0)) * K_TOT;
    // B staging roles (R1 verbatim): k row = tid>>5, n-offset (tid&31)*4
    int bk = tid >> 5;
    int bn = (tid & 31) * 4;

    float acc[4][4][4];
#pragma unroll
    for (int mt = 0; mt < 4; mt++)
#pragma unroll
        for (int nt = 0; nt < 4; nt++)
#pragma unroll
            for (int j = 0; j < 4; j++) acc[mt][nt][j] = 0.f;

    for (int ch = 0; ch < NCH; ch++) {
        int k0 = ch * BK;
        // ---- stage (same addressing as the passing R1 kernel, 16 k per chunk)
        float4 av0 = *(const float4*)(arow + k0 + ak);
        float4 av1 = *(const float4*)(arow + k0 + 8 + ak);
        As[ak + 0][ar] = av0.x; As[ak + 1][ar] = av0.y;
        As[ak + 2][ar] = av0.z; As[ak + 3][ar] = av0.w;
        As[8 + ak + 0][ar] = av1.x; As[8 + ak + 1][ar] = av1.y;
        As[8 + ak + 2][ar] = av1.z; As[8 + ak + 3][ar] = av1.w;
        *(float4*)&Bs[bk][bn]     = *(const float4*)(B + (size_t)(k0 + bk) * N_TOT + n0 + bn);
        *(float4*)&Bs[bk + 8][bn] = *(const float4*)(B + (size_t)(k0 + bk + 8) * N_TOT + n0 + bn);
        __syncthreads();

        // ---- compute: 2 x k8 steps, 3xTF32 split mma
#pragma unroll
        for (int s = 0; s < 2; s++) {
            int kb = s * 8;
            uint32_t bh[4][2], bl[4][2];
#pragma unroll
            for (int nt = 0; nt < 4; nt++) {
                split_tf32(Bs[kb + tg][wn + nt * 8 + gid],     bh[nt][0], bl[nt][0]);
                split_tf32(Bs[kb + tg + 4][wn + nt * 8 + gid], bh[nt][1], bl[nt][1]);
            }
#pragma unroll
            for (int mt = 0; mt < 4; mt++) {
                uint32_t ah[4], al[4];
                split_tf32(As[kb + tg][wm + mt * 16 + gid],         ah[0], al[0]);
                split_tf32(As[kb + tg][wm + mt * 16 + gid + 8],     ah[1], al[1]);
                split_tf32(As[kb + tg + 4][wm + mt * 16 + gid],     ah[2], al[2]);
                split_tf32(As[kb + tg + 4][wm + mt * 16 + gid + 8], ah[3], al[3]);
#pragma unroll
                for (int nt = 0; nt < 4; nt++) {
                    mma_tf32(acc[mt][nt], ah, bh[nt][0], bh[nt][1]);
                    mma_tf32(acc[mt][nt], ah, bl[nt][0], bl[nt][1]);
                    mma_tf32(acc[mt][nt], al, bh[nt][0], bh[nt][1]);
                }
            }
        }
        __syncthreads();
    }

    // ---- epilogue (fragment c0,c1 -> row gid, cols 2*tg,+1; c2,c3 -> row gid+8)
    const float* bp = bias + (size_t)e * N_TOT + n0;
#pragma unroll
    for (int mt = 0; mt < 4; mt++) {
#pragma unroll
        for (int half = 0; half < 2; half++) {
            int m = m0 + wm + mt * 16 + gid + half * 8;
            if (m >= cnt) continue;
#pragma unroll
            for (int nt = 0; nt < 4; nt++) {
                int col = wn + nt * 8 + tg * 2;
                float v0 = acc[mt][nt][half * 2 + 0] + bp[col];
                float v1 = acc[mt][nt][half * 2 + 1] + bp[col + 1];
                if (G1) {
                    float2 g;
                    g.x = gelu_tanh(v0);
                    g.y = gelu_tanh(v1);
                    *(float2*)(d_hbuf + (size_t)(off + m) * F_DIM + n0 + col) = g;
                } else {
                    float2 v; v.x = v0; v.y = v1;
                    *(float2*)(d_ybuf + (size_t)(off + m) * H_DIM + n0 + col) = v;
                }
            }
        }
    }
}

__global__ void combine_kernel(float* __restrict__ out) {
    int idx = blockIdx.x * blockDim.x + threadIdx.x;
    if (idx >= T_TOK * (H_DIM / 4)) return;
    int t  = idx >> 8;
    int n4 = idx & 255;
    int   s0 = d_slot[2 * t + 0], s1 = d_slot[2 * t + 1];
    float w0 = d_wt[2 * t + 0],  w1 = d_wt[2 * t + 1];
    float4 a = *(const float4*)(d_ybuf + (size_t)s0 * H_DIM + n4 * 4);
    float4 b = *(const float4*)(d_ybuf + (size_t)s1 * H_DIM + n4 * 4);
    float4 o;
    o.x = w0 * a.x + w1 * b.x;
    o.y = w0 * a.y + w1 * b.y;
    o.z = w0 * a.z + w1 * b.z;
    o.w = w0 * a.w + w1 * b.w;
    *(float4*)(out + (size_t)t * H_DIM + n4 * 4) = o;
}

// ---------------- launch -----------------------------------------------------
extern "C" void kernel_launch(void* const* d_in, const int* in_sizes, int n_in,
                              void* d_out, int out_size) {
    const float* x  = (const float*)d_in[0];
    const float* rw = (const float*)d_in[1];
    const float* rb = (const float*)d_in[2];
    const float* w1 = (const float*)d_in[3];
    const float* b1 = (const float*)d_in[4];
    const float* w2 = (const float*)d_in[5];
    const float* b2 = (const float*)d_in[6];
    float* out = (float*)d_out;

    init_kernel<<<1, 32>>>();
    router_kernel<<<T_TOK / 4, 128>>>(x, rw, rb);
    offsets_kernel<<<1, 32>>>();
    scatter_kernel<<<(T_TOK + 255) / 256, 256>>>();

    dim3 g1(F_DIM / 128, T_TOK / 128, E_NUM);   // (32, 64, 8)
    moe_gemm<true><<<g1, 256>>>(x, w1, b1);
    dim3 g2(H_DIM / 128, T_TOK / 128, E_NUM);   // (8, 64, 8)
    moe_gemm<false><<<g2, 256>>>(x, w2, b2);

    combine_kernel<<<(T_TOK * (H_DIM / 4) + 255) / 256, 256>>>(out);
}